// round 1
// baseline (speedup 1.0000x reference)
#include <cuda_runtime.h>
#include <math.h>

// Problem dims (fixed by setup_inputs)
#define B_   4
#define T_   2048
#define H_   1024
#define O_   1024
#define S_   128
#define NTOK (B_*T_)     // 8192
#define NC   16          // scan chunks
#define CL   128         // chunk length (NC*CL == T_)

// ---------------- scratch (device globals; no allocation allowed) ------------
__device__ float g_h[NTOK*2*H_];     // GEMM1 output [N, 2H]
__device__ float g_x1[NTOK*H_];      // gated input
__device__ float g_fwd[NTOK*H_];     // forward strand output
__device__ float g_bscan[NTOK*H_];   // provisional backward scan
__device__ float g_bwd[NTOK*H_];     // backward strand output
__device__ float g_mem[NTOK*H_];     // memory readout (pre-gate)
__device__ float g_wsum[NTOK*H_];    // fused weighted sum
__device__ float g_logits[NTOK*S_];  // slot logits / softmax (in place)
__device__ float g_gate[NTOK];       // entropy gate
__device__ float g_mgate[NTOK];      // memory gate
__device__ float g_carryB[B_*NC*H_];
__device__ float g_carryIn[B_*NC*H_];
__device__ float g_bank[S_*H_];      // decayed memory bank

__device__ __forceinline__ float sigmoidf_(float x) { return 1.f / (1.f + expf(-x)); }
__device__ __forceinline__ float siluf_(float x)    { return x / (1.f + expf(-x)); }

// ---------------- generic fp32 SGEMM: C = A[MxK] * B[KxN] (+bias) -----------
// BM=128 BN=128 BK=8, 256 threads, 8x8 per thread. Requires M%128==N%128==0, K%8==0.
#define BM 128
#define BN 128
#define BK 8
#define TM 8
#define TN 8

__global__ __launch_bounds__(256) void sgemm_kernel(
    const float* __restrict__ A, const float* __restrict__ B,
    const float* __restrict__ bias, float* __restrict__ C,
    int M, int N, int K)
{
    __shared__ float As[BK][BM];
    __shared__ float Bs[BK][BN];
    const int tid  = threadIdx.x;
    const int brow = blockIdx.y * BM;
    const int bcol = blockIdx.x * BN;

    const int a_row = tid >> 1;          // 0..127
    const int a_col = (tid & 1) * 4;     // 0 or 4
    const int b_row = tid >> 5;          // 0..7
    const int b_col = (tid & 31) * 4;    // 0..124

    const int ty = tid >> 4;             // 0..15
    const int tx = tid & 15;             // 0..15

    float acc[TM][TN];
    #pragma unroll
    for (int i = 0; i < TM; i++)
        #pragma unroll
        for (int j = 0; j < TN; j++) acc[i][j] = 0.f;

    const float* Aptr = A + (long)(brow + a_row) * K + a_col;
    const float* Bptr = B + (long)b_row * N + bcol + b_col;

    for (int k0 = 0; k0 < K; k0 += BK) {
        float4 av = *(const float4*)(Aptr + k0);
        float4 bv = *(const float4*)(Bptr + (long)k0 * N);
        As[a_col + 0][a_row] = av.x;
        As[a_col + 1][a_row] = av.y;
        As[a_col + 2][a_row] = av.z;
        As[a_col + 3][a_row] = av.w;
        *(float4*)&Bs[b_row][b_col] = bv;
        __syncthreads();
        #pragma unroll
        for (int kk = 0; kk < BK; kk++) {
            float ra[TM], rb[TN];
            #pragma unroll
            for (int i = 0; i < TM; i++) ra[i] = As[kk][ty * TM + i];
            #pragma unroll
            for (int j = 0; j < TN; j++) rb[j] = Bs[kk][tx * TN + j];
            #pragma unroll
            for (int i = 0; i < TM; i++)
                #pragma unroll
                for (int j = 0; j < TN; j++) acc[i][j] += ra[i] * rb[j];
        }
        __syncthreads();
    }

    #pragma unroll
    for (int i = 0; i < TM; i++) {
        int r = brow + ty * TM + i;
        #pragma unroll
        for (int j = 0; j < TN; j += 4) {
            int c = bcol + tx * TN + j;
            float4 v = make_float4(acc[i][j], acc[i][j+1], acc[i][j+2], acc[i][j+3]);
            if (bias) { v.x += bias[c]; v.y += bias[c+1]; v.z += bias[c+2]; v.w += bias[c+3]; }
            *(float4*)&C[(long)r * N + c] = v;
        }
    }
}

// ---------------- torsion split: x1 = a * silu(dt + dt_bias) -----------------
__global__ __launch_bounds__(256) void torsion_kernel(const float* __restrict__ dtb)
{
    int idx = blockIdx.x * 256 + threadIdx.x;       // NTOK*H
    int n = idx >> 10;
    int h = idx & (H_ - 1);
    float a  = g_h[(long)n * (2*H_) + h];
    float dt = g_h[(long)n * (2*H_) + H_ + h] + dtb[h];
    g_x1[idx] = a * siluf_(dt);
}

// ---------------- forward scan: conv(k=2)+silu then EMA ----------------------
// Pass A: per-chunk provisional scan. idx = (b*NC + c)*H + h
__global__ __launch_bounds__(256) void fwd_scanA(const float* __restrict__ conv_k,
                                                 const float* __restrict__ decay_fwd)
{
    int idx = blockIdx.x * 256 + threadIdx.x;
    int h = idx & (H_ - 1);
    int c = (idx >> 10) & (NC - 1);
    int b = idx >> 14;
    float d   = sigmoidf_(decay_fwd[h]);
    float omd = 1.f - d;
    float k0 = conv_k[2*h], k1 = conv_k[2*h + 1];
    long base = (long)b * T_ * H_ + h;
    int t0 = c * CL;
    float xprev = (t0 == 0) ? 0.f : g_x1[base + (long)(t0 - 1) * H_];
    float hloc = 0.f;
    #pragma unroll 4
    for (int i = 0; i < CL; i++) {
        float xc = g_x1[base + (long)(t0 + i) * H_];
        float y  = siluf_(k0 * xprev + k1 * xc);
        hloc = d * hloc + omd * y;
        g_fwd[base + (long)(t0 + i) * H_] = hloc;
        xprev = xc;
    }
    g_carryB[idx] = hloc;
}

// Pass B: scan carries across chunks. idx = b*H + h
__global__ __launch_bounds__(256) void fwd_scanB(const float* __restrict__ decay)
{
    int idx = blockIdx.x * 256 + threadIdx.x;   // B*H
    int h = idx & (H_ - 1);
    int b = idx >> 10;
    float d = sigmoidf_(decay[h]);
    float A = d;
    #pragma unroll
    for (int i = 0; i < 7; i++) A *= A;          // d^128
    float carry = 0.f;
    for (int c = 0; c < NC; c++) {
        int ci = (b * NC + c) * H_ + h;
        g_carryIn[ci] = carry;
        carry = A * carry + g_carryB[ci];
    }
}

// Pass C: fixup fwd with carry-in. idx = (b*NC + c)*H + h
__global__ __launch_bounds__(256) void fwd_scanC(const float* __restrict__ decay_fwd)
{
    int idx = blockIdx.x * 256 + threadIdx.x;
    int c = (idx >> 10) & (NC - 1);
    if (c == 0) return;
    int h = idx & (H_ - 1);
    int b = idx >> 14;
    float cin = g_carryIn[idx];
    float d = sigmoidf_(decay_fwd[h]);
    long base = (long)b * T_ * H_ + h;
    int t0 = c * CL;
    float p = d;
    #pragma unroll 4
    for (int i = 0; i < CL; i++) {
        g_fwd[base + (long)(t0 + i) * H_] += p * cin;
        p *= d;
    }
}

// ---------------- entropy gate + memory gate (block per token) ---------------
__global__ __launch_bounds__(256) void entropy_kernel(
    const float* __restrict__ Wmg, const float* __restrict__ bmg,
    const float* __restrict__ sw,  const float* __restrict__ sb)
{
    int n = blockIdx.x;
    int tid = threadIdx.x;
    const float* row = g_fwd + (long)n * H_;
    float v[4];
    float lmax = -1e30f;
    #pragma unroll
    for (int i = 0; i < 4; i++) { v[i] = row[tid + 256*i]; lmax = fmaxf(lmax, v[i]); }
    __shared__ float smax[256];
    smax[tid] = lmax; __syncthreads();
    for (int s = 128; s > 0; s >>= 1) {
        if (tid < s) smax[tid] = fmaxf(smax[tid], smax[tid + s]);
        __syncthreads();
    }
    float m = smax[0];
    float z = 0.f, fz = 0.f, dot = 0.f;
    #pragma unroll
    for (int i = 0; i < 4; i++) {
        float e = expf(v[i] - m);
        z += e; fz += v[i] * e;
        dot += v[i] * Wmg[tid + 256*i];
    }
    __shared__ float sz[256], sfz[256], sd[256];
    sz[tid] = z; sfz[tid] = fz; sd[tid] = dot; __syncthreads();
    for (int s = 128; s > 0; s >>= 1) {
        if (tid < s) { sz[tid] += sz[tid+s]; sfz[tid] += sfz[tid+s]; sd[tid] += sd[tid+s]; }
        __syncthreads();
    }
    if (tid == 0) {
        float Z   = sz[0];
        float lse = m + logf(Z);
        float ent = lse - sfz[0] / Z;
        g_gate[n]  = sigmoidf_(sw[0] * ent + sb[0]);
        g_mgate[n] = sigmoidf_(sd[0] + bmg[0]);
    }
}

// ---------------- softmax over S=128 (warp per row) --------------------------
__global__ __launch_bounds__(256) void softmax128_kernel()
{
    int gwarp = (blockIdx.x * 256 + threadIdx.x) >> 5;
    int lane  = threadIdx.x & 31;
    if (gwarp >= NTOK) return;
    float* row = g_logits + (long)gwarp * S_;
    float v[4];
    float m = -1e30f;
    #pragma unroll
    for (int i = 0; i < 4; i++) { v[i] = row[lane + 32*i]; m = fmaxf(m, v[i]); }
    #pragma unroll
    for (int o = 16; o > 0; o >>= 1) m = fmaxf(m, __shfl_xor_sync(0xffffffffu, m, o));
    float z = 0.f;
    float e[4];
    #pragma unroll
    for (int i = 0; i < 4; i++) { e[i] = expf(v[i] - m); z += e[i]; }
    #pragma unroll
    for (int o = 16; o > 0; o >>= 1) z += __shfl_xor_sync(0xffffffffu, z, o);
    float inv = 1.f / z;
    #pragma unroll
    for (int i = 0; i < 4; i++) row[lane + 32*i] = e[i] * inv;
}

// ---------------- decayed memory bank ----------------------------------------
__global__ __launch_bounds__(256) void bank_kernel(const float* __restrict__ memory,
                                                   const float* __restrict__ mem_decay)
{
    int idx = blockIdx.x * 256 + threadIdx.x;   // S*H
    int s = idx >> 10;
    g_bank[idx] = memory[idx] * sigmoidf_(mem_decay[s]);
}

// ---------------- backward scan over reversed fwd_out ------------------------
__global__ __launch_bounds__(256) void bwd_scanA(const float* __restrict__ decay_bwd)
{
    int idx = blockIdx.x * 256 + threadIdx.x;
    int h = idx & (H_ - 1);
    int c = (idx >> 10) & (NC - 1);
    int b = idx >> 14;
    float d   = sigmoidf_(decay_bwd[h]);
    float omd = 1.f - d;
    long base = (long)b * T_ * H_ + h;
    float hloc = 0.f;
    #pragma unroll 4
    for (int i = 0; i < CL; i++) {
        int u = c * CL + i;
        int t = T_ - 1 - u;
        float xc = g_fwd[base + (long)t * H_];
        hloc = d * hloc + omd * xc;
        g_bscan[base + (long)t * H_] = hloc;
    }
    g_carryB[idx] = hloc;
}

__global__ __launch_bounds__(256) void bwd_scanC(const float* __restrict__ decay_bwd)
{
    int idx = blockIdx.x * 256 + threadIdx.x;
    int h = idx & (H_ - 1);
    int c = (idx >> 10) & (NC - 1);
    int b = idx >> 14;
    float d = sigmoidf_(decay_bwd[h]);
    float cin = g_carryIn[idx];
    long base = (long)b * T_ * H_ + h;
    float p = d;
    #pragma unroll 4
    for (int i = 0; i < CL; i++) {
        int u = c * CL + i;
        int t = T_ - 1 - u;
        long pos = base + (long)t * H_;
        float s = g_bscan[pos] + p * cin;
        g_bwd[pos] = (g_fwd[pos] - s) * g_gate[b * T_ + t];
        p *= d;
    }
}

// ---------------- fusion ------------------------------------------------------
__global__ __launch_bounds__(256) void fusion_kernel(const float* __restrict__ fw)
{
    int idx = blockIdx.x * 256 + threadIdx.x;   // NTOK*H
    int n = idx >> 10;
    float w = fw[0] * g_fwd[idx] + fw[1] * g_bwd[idx]
            + fw[2] * (g_mem[idx] * g_mgate[n]);
    g_wsum[idx] = w;
}

// =============================================================================
static float* sym_addr(const void* symbol) {
    void* p = nullptr;
    cudaGetSymbolAddress(&p, symbol);
    return (float*)p;
}

extern "C" void kernel_launch(void* const* d_in, const int* in_sizes, int n_in,
                              void* d_out, int out_size)
{
    const float* x          = (const float*)d_in[0];
    const float* W_in       = (const float*)d_in[1];
    const float* b_in       = (const float*)d_in[2];
    const float* dt_bias    = (const float*)d_in[3];
    const float* conv_k     = (const float*)d_in[4];
    const float* decay_fwd  = (const float*)d_in[5];
    const float* decay_bwd  = (const float*)d_in[6];
    const float* memory     = (const float*)d_in[7];
    const float* mem_decay  = (const float*)d_in[8];
    const float* W_mem_gate = (const float*)d_in[9];
    const float* b_mem_gate = (const float*)d_in[10];
    // d_in[11], d_in[12]: W_slot, b_slot — unused by reference
    const float* W_slot_bwd = (const float*)d_in[13];
    const float* b_slot_bwd = (const float*)d_in[14];
    const float* fusion_w   = (const float*)d_in[15];
    const float* scaler_w   = (const float*)d_in[16];
    const float* scaler_b   = (const float*)d_in[17];
    const float* W_out      = (const float*)d_in[18];
    const float* b_out      = (const float*)d_in[19];
    float* out = (float*)d_out;

    float* p_h      = sym_addr(g_h);
    float* p_fwd    = sym_addr(g_fwd);
    float* p_logits = sym_addr(g_logits);
    float* p_bank   = sym_addr(g_bank);
    float* p_mem    = sym_addr(g_mem);
    float* p_wsum   = sym_addr(g_wsum);

    // 1) GEMM1: h = x @ W_in + b_in   [8192 x 2048]
    {
        dim3 grid(2*H_/BN, NTOK/BM);
        sgemm_kernel<<<grid, 256>>>(x, W_in, b_in, p_h, NTOK, 2*H_, H_);
    }
    // 2) torsion split
    torsion_kernel<<<NTOK*H_/256, 256>>>(dt_bias);
    // 3) forward scan (conv + silu + EMA)
    fwd_scanA<<<B_*NC*H_/256, 256>>>(conv_k, decay_fwd);
    fwd_scanB<<<B_*H_/256, 256>>>(decay_fwd);
    fwd_scanC<<<B_*NC*H_/256, 256>>>(decay_fwd);
    // 4) entropy gate + memory gate
    entropy_kernel<<<NTOK, 256>>>(W_mem_gate, b_mem_gate, scaler_w, scaler_b);
    // 5) slot logits GEMM + softmax
    {
        dim3 grid(S_/BN, NTOK/BM);
        sgemm_kernel<<<grid, 256>>>(p_fwd, W_slot_bwd, b_slot_bwd, p_logits, NTOK, S_, H_);
    }
    softmax128_kernel<<<NTOK*32/256, 256>>>();
    // 6) memory bank + read
    bank_kernel<<<S_*H_/256, 256>>>(memory, mem_decay);
    {
        dim3 grid(H_/BN, NTOK/BM);
        sgemm_kernel<<<grid, 256>>>(p_logits, p_bank, nullptr, p_mem, NTOK, H_, S_);
    }
    // 7) backward scan (on reversed fwd) + contrast + gate
    bwd_scanA<<<B_*NC*H_/256, 256>>>(decay_bwd);
    fwd_scanB<<<B_*H_/256, 256>>>(decay_bwd);   // same carry scan, bwd decay
    bwd_scanC<<<B_*NC*H_/256, 256>>>(decay_bwd);
    // 8) fusion
    fusion_kernel<<<NTOK*H_/256, 256>>>(fusion_w);
    // 9) GEMM2: out = weighted @ W_out + b_out
    {
        dim3 grid(O_/BN, NTOK/BM);
        sgemm_kernel<<<grid, 256>>>(p_wsum, W_out, b_out, out, NTOK, O_, H_);
    }
}

// round 3
// speedup vs baseline: 1.8045x; 1.8045x over previous
#include <cuda_runtime.h>
#include <cuda_bf16.h>
#include <math.h>
#include <stdint.h>

// Problem dims (fixed by setup_inputs)
#define B_   4
#define T_   2048
#define H_   1024
#define O_   1024
#define S_   128
#define NTOK (B_*T_)     // 8192
#define NC   16          // scan chunks
#define CL   128         // chunk length (NC*CL == T_)

// ---------------- scratch (device globals; no allocation allowed) ------------
__device__ float g_h[NTOK*2*H_];     // GEMM1 output [N, 2H]
__device__ float g_x1[NTOK*H_];      // gated input
__device__ float g_fwd[NTOK*H_];     // forward strand output
__device__ float g_bscan[NTOK*H_];   // provisional backward scan
__device__ float g_bwd[NTOK*H_];     // backward strand output
__device__ float g_mem[NTOK*H_];     // memory readout (pre-gate)
__device__ float g_wsum[NTOK*H_];    // fused weighted sum
__device__ float g_logits[NTOK*S_];  // slot logits / softmax (in place)
__device__ float g_gate[NTOK];       // entropy gate
__device__ float g_mgate[NTOK];      // memory gate
__device__ float g_carryB[B_*NC*H_];
__device__ float g_carryIn[B_*NC*H_];
__device__ float g_WtIn[2*H_*H_];    // W_in^T  [2H, H]
__device__ float g_WtOut[O_*H_];     // W_out^T [O, H]
__device__ float g_WtSlot[S_*H_];    // W_slot_bwd^T [S, H]
__device__ float g_bankT[H_*S_];     // (memory*sig(decay))^T [H, S]

__device__ __forceinline__ float sigmoidf_(float x) { return 1.f / (1.f + expf(-x)); }
__device__ __forceinline__ float siluf_(float x)    { return x / (1.f + expf(-x)); }

// ======================= mma.sync bf16 GEMM ==================================
// C[M,N] = A[M,K] @ Bt[N,K]^T (+bias), fp32 in/out.
// Split precision: A = Ah + Al, B = Bh + Bl (bf16); acc += AhBh + AhBl + AlBh.
// CTA tile 128x128, K chunk 32. 8 warps: 4 (m) x 2 (n); warp tile 32x64.
// smem: 4 tiles of [128 rows x 32 bf16] with 80B row pitch (conflict-free ldmatrix).

#define PITCH 80
#define TILE_BYTES_ (128 * PITCH)          // 10240
#define SM_AH 0
#define SM_AL (TILE_BYTES_)
#define SM_BH (2 * TILE_BYTES_)
#define SM_BL (3 * TILE_BYTES_)
#define GEMM_SMEM (4 * TILE_BYTES_)        // 40960

__device__ __forceinline__ uint32_t smem_u32(const void* p) {
    uint32_t a;
    asm("{ .reg .u64 t; cvta.to.shared.u64 t, %1; cvt.u32.u64 %0, t; }" : "=r"(a) : "l"(p));
    return a;
}

__device__ __forceinline__ void ldm_x4(uint32_t* r, uint32_t addr) {
    asm volatile("ldmatrix.sync.aligned.m8n8.x4.shared.b16 {%0,%1,%2,%3}, [%4];"
                 : "=r"(r[0]), "=r"(r[1]), "=r"(r[2]), "=r"(r[3]) : "r"(addr));
}

__device__ __forceinline__ void mma_bf16(float* c, const uint32_t* a, const uint32_t* b) {
    asm volatile("mma.sync.aligned.m16n8k16.row.col.f32.bf16.bf16.f32 "
                 "{%0,%1,%2,%3}, {%4,%5,%6,%7}, {%8,%9}, {%0,%1,%2,%3};"
                 : "+f"(c[0]), "+f"(c[1]), "+f"(c[2]), "+f"(c[3])
                 : "r"(a[0]), "r"(a[1]), "r"(a[2]), "r"(a[3]), "r"(b[0]), "r"(b[1]));
}

__device__ __forceinline__ void split_pack(float4 v, uint2& hi, uint2& lo) {
    __nv_bfloat16 h0 = __float2bfloat16(v.x), h1 = __float2bfloat16(v.y);
    __nv_bfloat16 h2 = __float2bfloat16(v.z), h3 = __float2bfloat16(v.w);
    __nv_bfloat16 g0 = __float2bfloat16(v.x - __bfloat162float(h0));
    __nv_bfloat16 g1 = __float2bfloat16(v.y - __bfloat162float(h1));
    __nv_bfloat16 g2 = __float2bfloat16(v.z - __bfloat162float(h2));
    __nv_bfloat16 g3 = __float2bfloat16(v.w - __bfloat162float(h3));
    hi.x = ((uint32_t)__bfloat16_as_ushort(h1) << 16) | __bfloat16_as_ushort(h0);
    hi.y = ((uint32_t)__bfloat16_as_ushort(h3) << 16) | __bfloat16_as_ushort(h2);
    lo.x = ((uint32_t)__bfloat16_as_ushort(g1) << 16) | __bfloat16_as_ushort(g0);
    lo.y = ((uint32_t)__bfloat16_as_ushort(g3) << 16) | __bfloat16_as_ushort(g2);
}

__global__ __launch_bounds__(256, 1) void gemm_mma(
    const float* __restrict__ A, const float* __restrict__ Bt,
    const float* __restrict__ bias, float* __restrict__ C,
    int K, int N)
{
    extern __shared__ char sm[];
    const int tid  = threadIdx.x;
    const int lane = tid & 31;
    const int wid  = tid >> 5;
    const int wm   = wid & 3;          // 0..3 -> m offset 32*wm
    const int wn   = wid >> 2;         // 0..1 -> n offset 64*wn
    const int brow = blockIdx.y * 128;
    const int bcol = blockIdx.x * 128;

    const uint32_t smb = smem_u32(sm);

    // per-thread ldmatrix addresses (within-tile byte offsets)
    // A: row = warp_m_base + (lane&15), col16 = lane>>4
    const uint32_t a_off = (uint32_t)((wm * 32 + (lane & 15)) * PITCH + (lane >> 4) * 16);
    // B: row = warp_n_base + (lane&7) + ((lane>>4)&1)*8, col16 = (lane>>3)&1
    const uint32_t b_off = (uint32_t)((wn * 64 + (lane & 7) + ((lane >> 4) & 1) * 8) * PITCH
                                      + ((lane >> 3) & 1) * 16);

    // gmem load mapping: 4 slots each for A and B; slot -> (row, float4-col)
    const int r0 = tid >> 3;           // 0..31, rows r0 + {0,32,64,96}
    const int c4 = tid & 7;            // float4 col within 32-float chunk
    const uint32_t st_off = (uint32_t)(c4 * 8);   // byte offset within row (hi/lo are 8B)

    float acc[2][8][4];
    #pragma unroll
    for (int i = 0; i < 2; i++)
        #pragma unroll
        for (int j = 0; j < 8; j++)
            #pragma unroll
            for (int q = 0; q < 4; q++) acc[i][j][q] = 0.f;

    const int nchunks = K >> 5;
    float4 pa[4], pb[4];

    // prefetch chunk 0
    #pragma unroll
    for (int s = 0; s < 4; s++) {
        int r = r0 + s * 32;
        pa[s] = __ldg((const float4*)(A  + (long)(brow + r) * K) + c4);
        pb[s] = __ldg((const float4*)(Bt + (long)(bcol + r) * K) + c4);
    }

    for (int c = 0; c < nchunks; c++) {
        __syncthreads();   // previous compute done; smem reusable
        #pragma unroll
        for (int s = 0; s < 4; s++) {
            int r = r0 + s * 32;
            uint32_t ro = (uint32_t)(r * PITCH) + st_off;
            uint2 hi, lo;
            split_pack(pa[s], hi, lo);
            *(uint2*)(sm + SM_AH + ro) = hi;
            *(uint2*)(sm + SM_AL + ro) = lo;
            split_pack(pb[s], hi, lo);
            *(uint2*)(sm + SM_BH + ro) = hi;
            *(uint2*)(sm + SM_BL + ro) = lo;
        }
        __syncthreads();

        if (c + 1 < nchunks) {
            int koff = (c + 1) << 3;   // float4 units
            #pragma unroll
            for (int s = 0; s < 4; s++) {
                int r = r0 + s * 32;
                pa[s] = __ldg((const float4*)(A  + (long)(brow + r) * K) + koff + c4);
                pb[s] = __ldg((const float4*)(Bt + (long)(bcol + r) * K) + koff + c4);
            }
        }

        #pragma unroll
        for (int ks = 0; ks < 2; ks++) {
            uint32_t kb = (uint32_t)(ks * 32);   // 16 bf16 = 32 bytes
            uint32_t ah[2][4], al[2][4];
            #pragma unroll
            for (int mt = 0; mt < 2; mt++) {
                uint32_t ao = a_off + (uint32_t)(mt * 16 * PITCH) + kb;
                ldm_x4(ah[mt], smb + SM_AH + ao);
                ldm_x4(al[mt], smb + SM_AL + ao);
            }
            #pragma unroll
            for (int np = 0; np < 4; np++) {
                uint32_t bo = b_off + (uint32_t)(np * 16 * PITCH) + kb;
                uint32_t bh[4], bl[4];
                ldm_x4(bh, smb + SM_BH + bo);
                ldm_x4(bl, smb + SM_BL + bo);
                #pragma unroll
                for (int mt = 0; mt < 2; mt++) {
                    mma_bf16(acc[mt][np*2  ], ah[mt], bh);
                    mma_bf16(acc[mt][np*2+1], ah[mt], bh + 2);
                    mma_bf16(acc[mt][np*2  ], ah[mt], bl);
                    mma_bf16(acc[mt][np*2+1], ah[mt], bl + 2);
                    mma_bf16(acc[mt][np*2  ], al[mt], bh);
                    mma_bf16(acc[mt][np*2+1], al[mt], bh + 2);
                }
            }
        }
    }

    // epilogue
    const int mrow = brow + wm * 32 + (lane >> 2);
    const int ncol0 = bcol + wn * 64 + (lane & 3) * 2;
    #pragma unroll
    for (int mt = 0; mt < 2; mt++) {
        int r = mrow + mt * 16;
        #pragma unroll
        for (int nn = 0; nn < 8; nn++) {
            int col = ncol0 + nn * 8;
            float b0 = bias ? bias[col] : 0.f;
            float b1 = bias ? bias[col + 1] : 0.f;
            float2 v0 = make_float2(acc[mt][nn][0] + b0, acc[mt][nn][1] + b1);
            float2 v1 = make_float2(acc[mt][nn][2] + b0, acc[mt][nn][3] + b1);
            *(float2*)(C + (long)r * N + col)       = v0;
            *(float2*)(C + (long)(r + 8) * N + col) = v1;
        }
    }
}

// ---------------- transpose: dst[c*R+r] = src[r*C+c] (* sigmoid(rowgate[r])) --
__global__ __launch_bounds__(256) void transpose_k(
    const float* __restrict__ src, float* __restrict__ dst,
    int R, int C, const float* __restrict__ rowgate)
{
    __shared__ float t[32][33];
    int bc = blockIdx.x * 32, br = blockIdx.y * 32;
    int x = threadIdx.x, y = threadIdx.y;   // 32 x 8
    #pragma unroll
    for (int i = 0; i < 32; i += 8) {
        float v = src[(long)(br + y + i) * C + bc + x];
        if (rowgate) v *= sigmoidf_(rowgate[br + y + i]);
        t[y + i][x] = v;
    }
    __syncthreads();
    #pragma unroll
    for (int i = 0; i < 32; i += 8)
        dst[(long)(bc + y + i) * R + br + x] = t[x][y + i];
}

// ---------------- torsion split: x1 = a * silu(dt + dt_bias) -----------------
__global__ __launch_bounds__(256) void torsion_kernel(const float* __restrict__ dtb)
{
    int idx = blockIdx.x * 256 + threadIdx.x;       // NTOK*H
    int n = idx >> 10;
    int h = idx & (H_ - 1);
    float a  = g_h[(long)n * (2*H_) + h];
    float dt = g_h[(long)n * (2*H_) + H_ + h] + dtb[h];
    g_x1[idx] = a * siluf_(dt);
}

// ---------------- forward scan: conv(k=2)+silu then EMA ----------------------
__global__ __launch_bounds__(256) void fwd_scanA(const float* __restrict__ conv_k,
                                                 const float* __restrict__ decay_fwd)
{
    int idx = blockIdx.x * 256 + threadIdx.x;
    int h = idx & (H_ - 1);
    int c = (idx >> 10) & (NC - 1);
    int b = idx >> 14;
    float d   = sigmoidf_(decay_fwd[h]);
    float omd = 1.f - d;
    float k0 = conv_k[2*h], k1 = conv_k[2*h + 1];
    long base = (long)b * T_ * H_ + h;
    int t0 = c * CL;
    float xprev = (t0 == 0) ? 0.f : g_x1[base + (long)(t0 - 1) * H_];
    float hloc = 0.f;
    #pragma unroll 4
    for (int i = 0; i < CL; i++) {
        float xc = g_x1[base + (long)(t0 + i) * H_];
        float y  = siluf_(k0 * xprev + k1 * xc);
        hloc = d * hloc + omd * y;
        g_fwd[base + (long)(t0 + i) * H_] = hloc;
        xprev = xc;
    }
    g_carryB[idx] = hloc;
}

__global__ __launch_bounds__(256) void fwd_scanB(const float* __restrict__ decay)
{
    int idx = blockIdx.x * 256 + threadIdx.x;   // B*H
    int h = idx & (H_ - 1);
    int b = idx >> 10;
    float d = sigmoidf_(decay[h]);
    float A = d;
    #pragma unroll
    for (int i = 0; i < 7; i++) A *= A;          // d^128
    float carry = 0.f;
    for (int c = 0; c < NC; c++) {
        int ci = (b * NC + c) * H_ + h;
        g_carryIn[ci] = carry;
        carry = A * carry + g_carryB[ci];
    }
}

__global__ __launch_bounds__(256) void fwd_scanC(const float* __restrict__ decay_fwd)
{
    int idx = blockIdx.x * 256 + threadIdx.x;
    int c = (idx >> 10) & (NC - 1);
    if (c == 0) return;
    int h = idx & (H_ - 1);
    int b = idx >> 14;
    float cin = g_carryIn[idx];
    float d = sigmoidf_(decay_fwd[h]);
    long base = (long)b * T_ * H_ + h;
    int t0 = c * CL;
    float p = d;
    #pragma unroll 4
    for (int i = 0; i < CL; i++) {
        g_fwd[base + (long)(t0 + i) * H_] += p * cin;
        p *= d;
    }
}

// ---------------- entropy gate + memory gate (block per token) ---------------
__global__ __launch_bounds__(256) void entropy_kernel(
    const float* __restrict__ Wmg, const float* __restrict__ bmg,
    const float* __restrict__ sw,  const float* __restrict__ sb)
{
    int n = blockIdx.x;
    int tid = threadIdx.x;
    const float* row = g_fwd + (long)n * H_;
    float v[4];
    float lmax = -1e30f;
    #pragma unroll
    for (int i = 0; i < 4; i++) { v[i] = row[tid + 256*i]; lmax = fmaxf(lmax, v[i]); }
    __shared__ float smax[256];
    smax[tid] = lmax; __syncthreads();
    for (int s = 128; s > 0; s >>= 1) {
        if (tid < s) smax[tid] = fmaxf(smax[tid], smax[tid + s]);
        __syncthreads();
    }
    float m = smax[0];
    float z = 0.f, fz = 0.f, dot = 0.f;
    #pragma unroll
    for (int i = 0; i < 4; i++) {
        float e = expf(v[i] - m);
        z += e; fz += v[i] * e;
        dot += v[i] * Wmg[tid + 256*i];
    }
    __shared__ float sz[256], sfz[256], sd[256];
    sz[tid] = z; sfz[tid] = fz; sd[tid] = dot; __syncthreads();
    for (int s = 128; s > 0; s >>= 1) {
        if (tid < s) { sz[tid] += sz[tid+s]; sfz[tid] += sfz[tid+s]; sd[tid] += sd[tid+s]; }
        __syncthreads();
    }
    if (tid == 0) {
        float Z   = sz[0];
        float lse = m + logf(Z);
        float ent = lse - sfz[0] / Z;
        g_gate[n]  = sigmoidf_(sw[0] * ent + sb[0]);
        g_mgate[n] = sigmoidf_(sd[0] + bmg[0]);
    }
}

// ---------------- softmax over S=128 (warp per row) --------------------------
__global__ __launch_bounds__(256) void softmax128_kernel()
{
    int gwarp = (blockIdx.x * 256 + threadIdx.x) >> 5;
    int lane  = threadIdx.x & 31;
    if (gwarp >= NTOK) return;
    float* row = g_logits + (long)gwarp * S_;
    float v[4];
    float m = -1e30f;
    #pragma unroll
    for (int i = 0; i < 4; i++) { v[i] = row[lane + 32*i]; m = fmaxf(m, v[i]); }
    #pragma unroll
    for (int o = 16; o > 0; o >>= 1) m = fmaxf(m, __shfl_xor_sync(0xffffffffu, m, o));
    float z = 0.f;
    float e[4];
    #pragma unroll
    for (int i = 0; i < 4; i++) { e[i] = expf(v[i] - m); z += e[i]; }
    #pragma unroll
    for (int o = 16; o > 0; o >>= 1) z += __shfl_xor_sync(0xffffffffu, z, o);
    float inv = 1.f / z;
    #pragma unroll
    for (int i = 0; i < 4; i++) row[lane + 32*i] = e[i] * inv;
}

// ---------------- backward scan over reversed fwd_out ------------------------
__global__ __launch_bounds__(256) void bwd_scanA(const float* __restrict__ decay_bwd)
{
    int idx = blockIdx.x * 256 + threadIdx.x;
    int h = idx & (H_ - 1);
    int c = (idx >> 10) & (NC - 1);
    int b = idx >> 14;
    float d   = sigmoidf_(decay_bwd[h]);
    float omd = 1.f - d;
    long base = (long)b * T_ * H_ + h;
    float hloc = 0.f;
    #pragma unroll 4
    for (int i = 0; i < CL; i++) {
        int u = c * CL + i;
        int t = T_ - 1 - u;
        float xc = g_fwd[base + (long)t * H_];
        hloc = d * hloc + omd * xc;
        g_bscan[base + (long)t * H_] = hloc;
    }
    g_carryB[idx] = hloc;
}

__global__ __launch_bounds__(256) void bwd_scanC(const float* __restrict__ decay_bwd)
{
    int idx = blockIdx.x * 256 + threadIdx.x;
    int h = idx & (H_ - 1);
    int c = (idx >> 10) & (NC - 1);
    int b = idx >> 14;
    float d = sigmoidf_(decay_bwd[h]);
    float cin = g_carryIn[idx];
    long base = (long)b * T_ * H_ + h;
    float p = d;
    #pragma unroll 4
    for (int i = 0; i < CL; i++) {
        int u = c * CL + i;
        int t = T_ - 1 - u;
        long pos = base + (long)t * H_;
        float s = g_bscan[pos] + p * cin;
        g_bwd[pos] = (g_fwd[pos] - s) * g_gate[b * T_ + t];
        p *= d;
    }
}

// ---------------- fusion ------------------------------------------------------
__global__ __launch_bounds__(256) void fusion_kernel(const float* __restrict__ fw)
{
    int idx = blockIdx.x * 256 + threadIdx.x;   // NTOK*H
    int n = idx >> 10;
    float w = fw[0] * g_fwd[idx] + fw[1] * g_bwd[idx]
            + fw[2] * (g_mem[idx] * g_mgate[n]);
    g_wsum[idx] = w;
}

// =============================================================================
static float* sym_addr(const void* symbol) {
    void* p = nullptr;
    cudaGetSymbolAddress(&p, symbol);
    return (float*)p;
}

extern "C" void kernel_launch(void* const* d_in, const int* in_sizes, int n_in,
                              void* d_out, int out_size)
{
    const float* x          = (const float*)d_in[0];
    const float* W_in       = (const float*)d_in[1];
    const float* b_in       = (const float*)d_in[2];
    const float* dt_bias    = (const float*)d_in[3];
    const float* conv_k     = (const float*)d_in[4];
    const float* decay_fwd  = (const float*)d_in[5];
    const float* decay_bwd  = (const float*)d_in[6];
    const float* memory     = (const float*)d_in[7];
    const float* mem_decay  = (const float*)d_in[8];
    const float* W_mem_gate = (const float*)d_in[9];
    const float* b_mem_gate = (const float*)d_in[10];
    // d_in[11], d_in[12]: W_slot, b_slot — unused by reference
    const float* W_slot_bwd = (const float*)d_in[13];
    const float* b_slot_bwd = (const float*)d_in[14];
    const float* fusion_w   = (const float*)d_in[15];
    const float* scaler_w   = (const float*)d_in[16];
    const float* scaler_b   = (const float*)d_in[17];
    const float* W_out      = (const float*)d_in[18];
    const float* b_out      = (const float*)d_in[19];
    float* out = (float*)d_out;

    float* p_h      = sym_addr(g_h);
    float* p_fwd    = sym_addr(g_fwd);
    float* p_logits = sym_addr(g_logits);
    float* p_mem    = sym_addr(g_mem);
    float* p_wsum   = sym_addr(g_wsum);
    float* p_WtIn   = sym_addr(g_WtIn);
    float* p_WtOut  = sym_addr(g_WtOut);
    float* p_WtSlot = sym_addr(g_WtSlot);
    float* p_bankT  = sym_addr(g_bankT);

    dim3 tb(32, 8);
    // weight transposes (to [N,K] K-major)
    transpose_k<<<dim3(2*H_/32, H_/32), tb>>>(W_in, p_WtIn, H_, 2*H_, nullptr);
    transpose_k<<<dim3(O_/32, H_/32), tb>>>(W_out, p_WtOut, H_, O_, nullptr);
    transpose_k<<<dim3(S_/32, H_/32), tb>>>(W_slot_bwd, p_WtSlot, H_, S_, nullptr);
    transpose_k<<<dim3(H_/32, S_/32), tb>>>(memory, p_bankT, S_, H_, mem_decay);

    // 1) GEMM1: h = x @ W_in + b_in   [8192 x 2048], K=1024
    gemm_mma<<<dim3(2*H_/128, NTOK/128), 256, GEMM_SMEM>>>(x, p_WtIn, b_in, p_h, H_, 2*H_);
    // 2) torsion split
    torsion_kernel<<<NTOK*H_/256, 256>>>(dt_bias);
    // 3) forward scan (conv + silu + EMA)
    fwd_scanA<<<B_*NC*H_/256, 256>>>(conv_k, decay_fwd);
    fwd_scanB<<<B_*H_/256, 256>>>(decay_fwd);
    fwd_scanC<<<B_*NC*H_/256, 256>>>(decay_fwd);
    // 4) entropy gate + memory gate
    entropy_kernel<<<NTOK, 256>>>(W_mem_gate, b_mem_gate, scaler_w, scaler_b);
    // 5) slot logits GEMM + softmax  [8192 x 128], K=1024
    gemm_mma<<<dim3(S_/128, NTOK/128), 256, GEMM_SMEM>>>(p_fwd, p_WtSlot, b_slot_bwd, p_logits, H_, S_);
    softmax128_kernel<<<NTOK*32/256, 256>>>();
    // 6) memory read GEMM  [8192 x 1024], K=128
    gemm_mma<<<dim3(H_/128, NTOK/128), 256, GEMM_SMEM>>>(p_logits, p_bankT, nullptr, p_mem, S_, H_);
    // 7) backward scan (on reversed fwd) + contrast + gate
    bwd_scanA<<<B_*NC*H_/256, 256>>>(decay_bwd);
    fwd_scanB<<<B_*H_/256, 256>>>(decay_bwd);
    bwd_scanC<<<B_*NC*H_/256, 256>>>(decay_bwd);
    // 8) fusion
    fusion_kernel<<<NTOK*H_/256, 256>>>(fusion_w);
    // 9) GEMM2: out = weighted @ W_out + b_out  [8192 x 1024], K=1024
    gemm_mma<<<dim3(O_/128, NTOK/128), 256, GEMM_SMEM>>>(p_wsum, p_WtOut, b_out, out, H_, O_);
}

// round 4
// speedup vs baseline: 1.8148x; 1.0057x over previous
#include <cuda_runtime.h>
#include <cuda_bf16.h>
#include <math.h>
#include <stdint.h>

// Problem dims (fixed by setup_inputs)
#define B_   4
#define T_   2048
#define H_   1024
#define O_   1024
#define S_   128
#define NTOK (B_*T_)     // 8192
#define NC   16          // scan chunks
#define CL   128         // chunk length (NC*CL == T_)

// ---------------- scratch (device globals; no allocation allowed) ------------
__device__ float g_h[NTOK*2*H_];     // GEMM1 output [N, 2H]
__device__ float g_fwd[NTOK*H_];     // forward strand output
__device__ float g_bscan[NTOK*H_];   // provisional backward scan
__device__ float g_mem[NTOK*H_];     // memory readout (pre-gate)
__device__ float g_wsum[NTOK*H_];    // fused weighted sum
__device__ float g_logits[NTOK*S_];  // slot logits / softmax (in place)
__device__ float g_gate[NTOK];       // entropy gate
__device__ float g_mgate[NTOK];      // memory gate
__device__ float g_carryB[B_*NC*H_];
__device__ float g_carryIn[B_*NC*H_];
__device__ float g_WtIn[2*H_*H_];    // W_in^T  [2H, H]
__device__ float g_WtOut[O_*H_];     // W_out^T [O, H]
__device__ float g_WtSlot[S_*H_];    // W_slot_bwd^T [S, H]
__device__ float g_bankT[H_*S_];     // (memory*sig(decay))^T [H, S]

__device__ __forceinline__ float sigmoidf_(float x) { return 1.f / (1.f + expf(-x)); }
__device__ __forceinline__ float siluf_(float x)    { return x / (1.f + expf(-x)); }

// ======================= mma.sync bf16 GEMM ==================================
// C[M,N] = A[M,K] @ Bt[N,K]^T (+bias), fp32 in/out.
// Split precision: A = Ah + Al, B = Bh + Bl (bf16); acc += AhBh + AhBl + AlBh.
// CTA tile 128x128, K chunk 32. 8 warps: 4 (m) x 2 (n); warp tile 32x64.
// smem: 4 tiles of [128 rows x 32 bf16] with 80B row pitch (conflict-free ldmatrix).

#define PITCH 80
#define TILE_BYTES_ (128 * PITCH)          // 10240
#define SM_AH 0
#define SM_AL (TILE_BYTES_)
#define SM_BH (2 * TILE_BYTES_)
#define SM_BL (3 * TILE_BYTES_)
#define GEMM_SMEM (4 * TILE_BYTES_)        // 40960

__device__ __forceinline__ uint32_t smem_u32(const void* p) {
    uint32_t a;
    asm("{ .reg .u64 t; cvta.to.shared.u64 t, %1; cvt.u32.u64 %0, t; }" : "=r"(a) : "l"(p));
    return a;
}

__device__ __forceinline__ void ldm_x4(uint32_t* r, uint32_t addr) {
    asm volatile("ldmatrix.sync.aligned.m8n8.x4.shared.b16 {%0,%1,%2,%3}, [%4];"
                 : "=r"(r[0]), "=r"(r[1]), "=r"(r[2]), "=r"(r[3]) : "r"(addr));
}

__device__ __forceinline__ void mma_bf16(float* c, const uint32_t* a, const uint32_t* b) {
    asm volatile("mma.sync.aligned.m16n8k16.row.col.f32.bf16.bf16.f32 "
                 "{%0,%1,%2,%3}, {%4,%5,%6,%7}, {%8,%9}, {%0,%1,%2,%3};"
                 : "+f"(c[0]), "+f"(c[1]), "+f"(c[2]), "+f"(c[3])
                 : "r"(a[0]), "r"(a[1]), "r"(a[2]), "r"(a[3]), "r"(b[0]), "r"(b[1]));
}

__device__ __forceinline__ void split_pack(float4 v, uint2& hi, uint2& lo) {
    __nv_bfloat16 h0 = __float2bfloat16(v.x), h1 = __float2bfloat16(v.y);
    __nv_bfloat16 h2 = __float2bfloat16(v.z), h3 = __float2bfloat16(v.w);
    __nv_bfloat16 g0 = __float2bfloat16(v.x - __bfloat162float(h0));
    __nv_bfloat16 g1 = __float2bfloat16(v.y - __bfloat162float(h1));
    __nv_bfloat16 g2 = __float2bfloat16(v.z - __bfloat162float(h2));
    __nv_bfloat16 g3 = __float2bfloat16(v.w - __bfloat162float(h3));
    hi.x = ((uint32_t)__bfloat16_as_ushort(h1) << 16) | __bfloat16_as_ushort(h0);
    hi.y = ((uint32_t)__bfloat16_as_ushort(h3) << 16) | __bfloat16_as_ushort(h2);
    lo.x = ((uint32_t)__bfloat16_as_ushort(g1) << 16) | __bfloat16_as_ushort(g0);
    lo.y = ((uint32_t)__bfloat16_as_ushort(g3) << 16) | __bfloat16_as_ushort(g2);
}

__global__ __launch_bounds__(256, 1) void gemm_mma(
    const float* __restrict__ A, const float* __restrict__ Bt,
    const float* __restrict__ bias, float* __restrict__ C,
    int K, int N)
{
    extern __shared__ char sm[];
    const int tid  = threadIdx.x;
    const int lane = tid & 31;
    const int wid  = tid >> 5;
    const int wm   = wid & 3;          // 0..3 -> m offset 32*wm
    const int wn   = wid >> 2;         // 0..1 -> n offset 64*wn
    const int brow = blockIdx.y * 128;
    const int bcol = blockIdx.x * 128;

    const uint32_t smb = smem_u32(sm);

    const uint32_t a_off = (uint32_t)((wm * 32 + (lane & 15)) * PITCH + (lane >> 4) * 16);
    const uint32_t b_off = (uint32_t)((wn * 64 + (lane & 7) + ((lane >> 4) & 1) * 8) * PITCH
                                      + ((lane >> 3) & 1) * 16);

    const int r0 = tid >> 3;           // 0..31, rows r0 + {0,32,64,96}
    const int c4 = tid & 7;            // float4 col within 32-float chunk
    const uint32_t st_off = (uint32_t)(c4 * 8);

    float acc[2][8][4];
    #pragma unroll
    for (int i = 0; i < 2; i++)
        #pragma unroll
        for (int j = 0; j < 8; j++)
            #pragma unroll
            for (int q = 0; q < 4; q++) acc[i][j][q] = 0.f;

    const int nchunks = K >> 5;
    float4 pa[4], pb[4];

    #pragma unroll
    for (int s = 0; s < 4; s++) {
        int r = r0 + s * 32;
        pa[s] = __ldg((const float4*)(A  + (long)(brow + r) * K) + c4);
        pb[s] = __ldg((const float4*)(Bt + (long)(bcol + r) * K) + c4);
    }

    for (int c = 0; c < nchunks; c++) {
        __syncthreads();
        #pragma unroll
        for (int s = 0; s < 4; s++) {
            int r = r0 + s * 32;
            uint32_t ro = (uint32_t)(r * PITCH) + st_off;
            uint2 hi, lo;
            split_pack(pa[s], hi, lo);
            *(uint2*)(sm + SM_AH + ro) = hi;
            *(uint2*)(sm + SM_AL + ro) = lo;
            split_pack(pb[s], hi, lo);
            *(uint2*)(sm + SM_BH + ro) = hi;
            *(uint2*)(sm + SM_BL + ro) = lo;
        }
        __syncthreads();

        if (c + 1 < nchunks) {
            int koff = (c + 1) << 3;
            #pragma unroll
            for (int s = 0; s < 4; s++) {
                int r = r0 + s * 32;
                pa[s] = __ldg((const float4*)(A  + (long)(brow + r) * K) + koff + c4);
                pb[s] = __ldg((const float4*)(Bt + (long)(bcol + r) * K) + koff + c4);
            }
        }

        #pragma unroll
        for (int ks = 0; ks < 2; ks++) {
            uint32_t kb = (uint32_t)(ks * 32);
            uint32_t ah[2][4], al[2][4];
            uint32_t bh[4][4], bl[4][4];
            #pragma unroll
            for (int mt = 0; mt < 2; mt++) {
                uint32_t ao = a_off + (uint32_t)(mt * 16 * PITCH) + kb;
                ldm_x4(ah[mt], smb + SM_AH + ao);
                ldm_x4(al[mt], smb + SM_AL + ao);
            }
            #pragma unroll
            for (int np = 0; np < 4; np++) {
                uint32_t bo = b_off + (uint32_t)(np * 16 * PITCH) + kb;
                ldm_x4(bh[np], smb + SM_BH + bo);
                ldm_x4(bl[np], smb + SM_BL + bo);
            }
            // term-major issue order: same-accumulator reuse distance = 16 MMAs
            #pragma unroll
            for (int np = 0; np < 4; np++)
                #pragma unroll
                for (int mt = 0; mt < 2; mt++) {
                    mma_bf16(acc[mt][np*2  ], ah[mt], bh[np]);
                    mma_bf16(acc[mt][np*2+1], ah[mt], bh[np] + 2);
                }
            #pragma unroll
            for (int np = 0; np < 4; np++)
                #pragma unroll
                for (int mt = 0; mt < 2; mt++) {
                    mma_bf16(acc[mt][np*2  ], ah[mt], bl[np]);
                    mma_bf16(acc[mt][np*2+1], ah[mt], bl[np] + 2);
                }
            #pragma unroll
            for (int np = 0; np < 4; np++)
                #pragma unroll
                for (int mt = 0; mt < 2; mt++) {
                    mma_bf16(acc[mt][np*2  ], al[mt], bh[np]);
                    mma_bf16(acc[mt][np*2+1], al[mt], bh[np] + 2);
                }
        }
    }

    // epilogue
    const int mrow = brow + wm * 32 + (lane >> 2);
    const int ncol0 = bcol + wn * 64 + (lane & 3) * 2;
    #pragma unroll
    for (int mt = 0; mt < 2; mt++) {
        int r = mrow + mt * 16;
        #pragma unroll
        for (int nn = 0; nn < 8; nn++) {
            int col = ncol0 + nn * 8;
            float b0 = bias ? bias[col] : 0.f;
            float b1 = bias ? bias[col + 1] : 0.f;
            float2 v0 = make_float2(acc[mt][nn][0] + b0, acc[mt][nn][1] + b1);
            float2 v1 = make_float2(acc[mt][nn][2] + b0, acc[mt][nn][3] + b1);
            *(float2*)(C + (long)r * N + col)       = v0;
            *(float2*)(C + (long)(r + 8) * N + col) = v1;
        }
    }
}

// ---------------- transpose: dst[c*R+r] = src[r*C+c] (* sigmoid(rowgate[r])) --
__global__ __launch_bounds__(256) void transpose_k(
    const float* __restrict__ src, float* __restrict__ dst,
    int R, int C, const float* __restrict__ rowgate)
{
    __shared__ float t[32][33];
    int bc = blockIdx.x * 32, br = blockIdx.y * 32;
    int x = threadIdx.x, y = threadIdx.y;   // 32 x 8
    #pragma unroll
    for (int i = 0; i < 32; i += 8) {
        float v = src[(long)(br + y + i) * C + bc + x];
        if (rowgate) v *= sigmoidf_(rowgate[br + y + i]);
        t[y + i][x] = v;
    }
    __syncthreads();
    #pragma unroll
    for (int i = 0; i < 32; i += 8)
        dst[(long)(bc + y + i) * R + br + x] = t[x][y + i];
}

// ------- forward scan fused with torsion: x1 computed inline from g_h --------
__device__ __forceinline__ float x1_at(long n, int h, const float* dtb) {
    float a  = g_h[n * (2*H_) + h];
    float dt = g_h[n * (2*H_) + H_ + h] + dtb[h];
    return a * siluf_(dt);
}

__global__ __launch_bounds__(256) void fwd_scanA(const float* __restrict__ conv_k,
                                                 const float* __restrict__ decay_fwd,
                                                 const float* __restrict__ dtb)
{
    int idx = blockIdx.x * 256 + threadIdx.x;
    int h = idx & (H_ - 1);
    int c = (idx >> 10) & (NC - 1);
    int b = idx >> 14;
    float d   = sigmoidf_(decay_fwd[h]);
    float omd = 1.f - d;
    float k0 = conv_k[2*h], k1 = conv_k[2*h + 1];
    long nbase = (long)b * T_;
    int t0 = c * CL;
    float xprev = (t0 == 0) ? 0.f : x1_at(nbase + t0 - 1, h, dtb);
    float hloc = 0.f;
    long obase = (long)b * T_ * H_ + h;
    #pragma unroll 2
    for (int i = 0; i < CL; i++) {
        float xc = x1_at(nbase + t0 + i, h, dtb);
        float y  = siluf_(k0 * xprev + k1 * xc);
        hloc = d * hloc + omd * y;
        g_fwd[obase + (long)(t0 + i) * H_] = hloc;
        xprev = xc;
    }
    g_carryB[idx] = hloc;
}

__global__ __launch_bounds__(256) void fwd_scanB(const float* __restrict__ decay)
{
    int idx = blockIdx.x * 256 + threadIdx.x;   // B*H
    int h = idx & (H_ - 1);
    int b = idx >> 10;
    float d = sigmoidf_(decay[h]);
    float A = d;
    #pragma unroll
    for (int i = 0; i < 7; i++) A *= A;          // d^128
    float carry = 0.f;
    for (int c = 0; c < NC; c++) {
        int ci = (b * NC + c) * H_ + h;
        g_carryIn[ci] = carry;
        carry = A * carry + g_carryB[ci];
    }
}

__global__ __launch_bounds__(256) void fwd_scanC(const float* __restrict__ decay_fwd)
{
    int idx = blockIdx.x * 256 + threadIdx.x;
    int c = (idx >> 10) & (NC - 1);
    if (c == 0) return;
    int h = idx & (H_ - 1);
    int b = idx >> 14;
    float cin = g_carryIn[idx];
    float d = sigmoidf_(decay_fwd[h]);
    long base = (long)b * T_ * H_ + h;
    int t0 = c * CL;
    float p = d;
    #pragma unroll 4
    for (int i = 0; i < CL; i++) {
        g_fwd[base + (long)(t0 + i) * H_] += p * cin;
        p *= d;
    }
}

// ---------------- entropy gate + memory gate (block per token) ---------------
__global__ __launch_bounds__(256) void entropy_kernel(
    const float* __restrict__ Wmg, const float* __restrict__ bmg,
    const float* __restrict__ sw,  const float* __restrict__ sb)
{
    int n = blockIdx.x;
    int tid = threadIdx.x;
    const float* row = g_fwd + (long)n * H_;
    float v[4];
    float lmax = -1e30f;
    #pragma unroll
    for (int i = 0; i < 4; i++) { v[i] = row[tid + 256*i]; lmax = fmaxf(lmax, v[i]); }
    __shared__ float smax[256];
    smax[tid] = lmax; __syncthreads();
    for (int s = 128; s > 0; s >>= 1) {
        if (tid < s) smax[tid] = fmaxf(smax[tid], smax[tid + s]);
        __syncthreads();
    }
    float m = smax[0];
    float z = 0.f, fz = 0.f, dot = 0.f;
    #pragma unroll
    for (int i = 0; i < 4; i++) {
        float e = expf(v[i] - m);
        z += e; fz += v[i] * e;
        dot += v[i] * Wmg[tid + 256*i];
    }
    __shared__ float sz[256], sfz[256], sd[256];
    sz[tid] = z; sfz[tid] = fz; sd[tid] = dot; __syncthreads();
    for (int s = 128; s > 0; s >>= 1) {
        if (tid < s) { sz[tid] += sz[tid+s]; sfz[tid] += sfz[tid+s]; sd[tid] += sd[tid+s]; }
        __syncthreads();
    }
    if (tid == 0) {
        float Z   = sz[0];
        float lse = m + logf(Z);
        float ent = lse - sfz[0] / Z;
        g_gate[n]  = sigmoidf_(sw[0] * ent + sb[0]);
        g_mgate[n] = sigmoidf_(sd[0] + bmg[0]);
    }
}

// ---------------- softmax over S=128 (warp per row) --------------------------
__global__ __launch_bounds__(256) void softmax128_kernel()
{
    int gwarp = (blockIdx.x * 256 + threadIdx.x) >> 5;
    int lane  = threadIdx.x & 31;
    if (gwarp >= NTOK) return;
    float* row = g_logits + (long)gwarp * S_;
    float v[4];
    float m = -1e30f;
    #pragma unroll
    for (int i = 0; i < 4; i++) { v[i] = row[lane + 32*i]; m = fmaxf(m, v[i]); }
    #pragma unroll
    for (int o = 16; o > 0; o >>= 1) m = fmaxf(m, __shfl_xor_sync(0xffffffffu, m, o));
    float z = 0.f;
    float e[4];
    #pragma unroll
    for (int i = 0; i < 4; i++) { e[i] = expf(v[i] - m); z += e[i]; }
    #pragma unroll
    for (int o = 16; o > 0; o >>= 1) z += __shfl_xor_sync(0xffffffffu, z, o);
    float inv = 1.f / z;
    #pragma unroll
    for (int i = 0; i < 4; i++) row[lane + 32*i] = e[i] * inv;
}

// ---------------- backward scan over reversed fwd_out ------------------------
__global__ __launch_bounds__(256) void bwd_scanA(const float* __restrict__ decay_bwd)
{
    int idx = blockIdx.x * 256 + threadIdx.x;
    int h = idx & (H_ - 1);
    int c = (idx >> 10) & (NC - 1);
    int b = idx >> 14;
    float d   = sigmoidf_(decay_bwd[h]);
    float omd = 1.f - d;
    long base = (long)b * T_ * H_ + h;
    float hloc = 0.f;
    #pragma unroll 4
    for (int i = 0; i < CL; i++) {
        int u = c * CL + i;
        int t = T_ - 1 - u;
        float xc = g_fwd[base + (long)t * H_];
        hloc = d * hloc + omd * xc;
        g_bscan[base + (long)t * H_] = hloc;
    }
    g_carryB[idx] = hloc;
}

// fixup + contrast + gate + three-way fusion, all in one pass
__global__ __launch_bounds__(256) void bwd_scanC_fused(const float* __restrict__ decay_bwd,
                                                       const float* __restrict__ fw)
{
    int idx = blockIdx.x * 256 + threadIdx.x;
    int h = idx & (H_ - 1);
    int c = (idx >> 10) & (NC - 1);
    int b = idx >> 14;
    float d = sigmoidf_(decay_bwd[h]);
    float cin = g_carryIn[idx];
    float f0 = fw[0], f1 = fw[1], f2 = fw[2];
    long base = (long)b * T_ * H_ + h;
    float p = d;
    #pragma unroll 2
    for (int i = 0; i < CL; i++) {
        int u = c * CL + i;
        int t = T_ - 1 - u;
        long pos = base + (long)t * H_;
        int n = b * T_ + t;
        float s    = g_bscan[pos] + p * cin;
        float fwdv = g_fwd[pos];
        float bwdv = (fwdv - s) * g_gate[n];
        g_wsum[pos] = f0 * fwdv + f1 * bwdv + f2 * (g_mem[pos] * g_mgate[n]);
        p *= d;
    }
}

// =============================================================================
static float* sym_addr(const void* symbol) {
    void* p = nullptr;
    cudaGetSymbolAddress(&p, symbol);
    return (float*)p;
}

extern "C" void kernel_launch(void* const* d_in, const int* in_sizes, int n_in,
                              void* d_out, int out_size)
{
    const float* x          = (const float*)d_in[0];
    const float* W_in       = (const float*)d_in[1];
    const float* b_in       = (const float*)d_in[2];
    const float* dt_bias    = (const float*)d_in[3];
    const float* conv_k     = (const float*)d_in[4];
    const float* decay_fwd  = (const float*)d_in[5];
    const float* decay_bwd  = (const float*)d_in[6];
    const float* memory     = (const float*)d_in[7];
    const float* mem_decay  = (const float*)d_in[8];
    const float* W_mem_gate = (const float*)d_in[9];
    const float* b_mem_gate = (const float*)d_in[10];
    // d_in[11], d_in[12]: W_slot, b_slot — unused by reference
    const float* W_slot_bwd = (const float*)d_in[13];
    const float* b_slot_bwd = (const float*)d_in[14];
    const float* fusion_w   = (const float*)d_in[15];
    const float* scaler_w   = (const float*)d_in[16];
    const float* scaler_b   = (const float*)d_in[17];
    const float* W_out      = (const float*)d_in[18];
    const float* b_out      = (const float*)d_in[19];
    float* out = (float*)d_out;

    float* p_h      = sym_addr(g_h);
    float* p_fwd    = sym_addr(g_fwd);
    float* p_logits = sym_addr(g_logits);
    float* p_mem    = sym_addr(g_mem);
    float* p_wsum   = sym_addr(g_wsum);
    float* p_WtIn   = sym_addr(g_WtIn);
    float* p_WtOut  = sym_addr(g_WtOut);
    float* p_WtSlot = sym_addr(g_WtSlot);
    float* p_bankT  = sym_addr(g_bankT);

    dim3 tb(32, 8);
    // weight transposes (to [N,K] K-major)
    transpose_k<<<dim3(2*H_/32, H_/32), tb>>>(W_in, p_WtIn, H_, 2*H_, nullptr);
    transpose_k<<<dim3(O_/32, H_/32), tb>>>(W_out, p_WtOut, H_, O_, nullptr);
    transpose_k<<<dim3(S_/32, H_/32), tb>>>(W_slot_bwd, p_WtSlot, H_, S_, nullptr);
    transpose_k<<<dim3(H_/32, S_/32), tb>>>(memory, p_bankT, S_, H_, mem_decay);

    // 1) GEMM1: h = x @ W_in + b_in   [8192 x 2048], K=1024
    gemm_mma<<<dim3(2*H_/128, NTOK/128), 256, GEMM_SMEM>>>(x, p_WtIn, b_in, p_h, H_, 2*H_);
    // 2) forward scan (torsion + conv + silu + EMA fused)
    fwd_scanA<<<B_*NC*H_/256, 256>>>(conv_k, decay_fwd, dt_bias);
    fwd_scanB<<<B_*H_/256, 256>>>(decay_fwd);
    fwd_scanC<<<B_*NC*H_/256, 256>>>(decay_fwd);
    // 3) entropy gate + memory gate
    entropy_kernel<<<NTOK, 256>>>(W_mem_gate, b_mem_gate, scaler_w, scaler_b);
    // 4) slot logits GEMM + softmax  [8192 x 128], K=1024
    gemm_mma<<<dim3(S_/128, NTOK/128), 256, GEMM_SMEM>>>(p_fwd, p_WtSlot, b_slot_bwd, p_logits, H_, S_);
    softmax128_kernel<<<NTOK*32/256, 256>>>();
    // 5) memory read GEMM  [8192 x 1024], K=128
    gemm_mma<<<dim3(H_/128, NTOK/128), 256, GEMM_SMEM>>>(p_logits, p_bankT, nullptr, p_mem, S_, H_);
    // 6) backward scan + contrast + gate + fusion (fused)
    bwd_scanA<<<B_*NC*H_/256, 256>>>(decay_bwd);
    fwd_scanB<<<B_*H_/256, 256>>>(decay_bwd);
    bwd_scanC_fused<<<B_*NC*H_/256, 256>>>(decay_bwd, fusion_w);
    // 7) GEMM2: out = weighted @ W_out + b_out  [8192 x 1024], K=1024
    gemm_mma<<<dim3(O_/128, NTOK/128), 256, GEMM_SMEM>>>(p_wsum, p_WtOut, b_out, out, H_, O_);
}